// round 8
// baseline (speedup 1.0000x reference)
#include <cuda_runtime.h>

#define NCAM 6
#define C    64
#define HF   64
#define WF   176
#define NY   4
#define ZD   129
#define XD   129
#define NH   3
#define DD   128
#define WDIM 128
#define NVOX (NH * DD * WDIM)   // 49152

// Scratch (static device globals: allocation-free per harness rules)
__device__ float  g_tmpi[NCAM * C * HF * WF];    // [n][c][h][w]
__device__ float  g_integ[NCAM * HF * WF * C];   // [n][h][w][c]
__device__ float2 g_nc[NCAM * NY * ZD * XD];     // projected corners

// ---------------------------------------------------------------------------
// Kernel 1: integral image per (n,c), coalesced channel-major write
// ---------------------------------------------------------------------------
__global__ void __launch_bounds__(256) integral_kernel(const float* __restrict__ feat) {
    __shared__ float tile[HF * WF];
    const int ncid = blockIdx.x;
    const int tid = threadIdx.x;

    const float* src = feat + (size_t)ncid * HF * WF;
    for (int i = tid; i < HF * WF; i += 256) tile[i] = src[i];
    __syncthreads();

    const int lane = tid & 31, wp = tid >> 5;
    for (int row = wp; row < HF; row += 8) {
        float carry = 0.f;
        #pragma unroll
        for (int seg = 0; seg < 6; seg++) {
            int w = seg * 32 + lane;
            float v = (w < WF) ? tile[row * WF + w] : 0.f;
            #pragma unroll
            for (int off = 1; off < 32; off <<= 1) {
                float u = __shfl_up_sync(0xffffffffu, v, off);
                if (lane >= off) v += u;
            }
            v += carry;
            if (w < WF) tile[row * WF + w] = v;
            carry = __shfl_sync(0xffffffffu, v, 31);
        }
    }
    __syncthreads();

    if (tid < WF) {
        float acc = 0.f;
        #pragma unroll 4
        for (int h = 0; h < HF; h++) {
            acc += tile[h * WF + tid];
            tile[h * WF + tid] = acc;
        }
    }
    __syncthreads();

    float* dst = g_tmpi + (size_t)ncid * HF * WF;
    for (int i = tid; i < HF * WF; i += 256) dst[i] = tile[i];
}

// ---------------------------------------------------------------------------
// Kernel 1b: transpose [n][c][h][w] -> [n][h][w][c]
// ---------------------------------------------------------------------------
__global__ void __launch_bounds__(256) transpose_kernel() {
    __shared__ float tile[C * 33];
    const int n  = blockIdx.z;
    const int h  = blockIdx.y;
    const int w0 = blockIdx.x * 32;

    const float* src = g_tmpi + ((size_t)n * C * HF + h) * WF;
    for (int idx = threadIdx.x; idx < C * 32; idx += 256) {
        int c = idx >> 5, w = idx & 31;
        int gw = w0 + w;
        tile[c * 33 + w] = (gw < WF) ? src[(size_t)c * HF * WF + gw] : 0.f;
    }
    __syncthreads();

    float* dst = g_integ + (((size_t)n * HF + h) * WF) * C;
    for (int idx = threadIdx.x; idx < C * 32; idx += 256) {
        int w = idx >> 6, c = idx & 63;
        int gw = w0 + w;
        if (gw < WF) dst[(size_t)gw * C + c] = tile[c * 33 + w];
    }
}

// ---------------------------------------------------------------------------
// Kernel 2: project grid corners
// ---------------------------------------------------------------------------
__global__ void proj_kernel(const float* __restrict__ ks,
                            const float* __restrict__ m2c,
                            const float* __restrict__ prot,
                            const float* __restrict__ ptran,
                            const float* __restrict__ und,
                            const float* __restrict__ grid) {
    const int id = blockIdx.x * blockDim.x + threadIdx.x;
    const int total = NCAM * NY * ZD * XD;
    if (id >= total) return;
    const int xi = id % XD;
    const int zi = (id / XD) % ZD;
    const int ny = (id / (XD * ZD)) % NY;
    const int n  = id / (XD * ZD * NY);

    const float* K  = ks    + n * 9;
    const float* M  = m2c   + n * 12;
    const float* PR = prot  + n * 9;
    const float* PT = ptran + n * 3;
    const float* Dd = und   + n * 7;

    float cal[3][4];
    #pragma unroll
    for (int i = 0; i < 3; i++)
        #pragma unroll
        for (int j = 0; j < 4; j++)
            cal[i][j] = K[i*3+0]*M[0*4+j] + K[i*3+1]*M[1*4+j] + K[i*3+2]*M[2*4+j];

    const float* g = grid + ((size_t)zi * XD + xi) * 3;
    const float vx = g[0];
    const float vy = g[1] + (2.0f - (float)ny);
    const float vz = g[2];

    float hx = cal[0][0]*vx + cal[0][1]*vy + cal[0][2]*vz + cal[0][3];
    float hy = cal[1][0]*vx + cal[1][1]*vy + cal[1][2]*vz + cal[1][3];
    float hz = cal[2][0]*vx + cal[2][1]*vy + cal[2][2]*vz + cal[2][3];

    const float posf = (hz > 0.f) ? 1.f : 0.f;
    hx *= posf; hy *= posf;
    const float px = hx / hz, py = hy / hz;

    const float cx = K[2], cy = K[5], fx = K[0], fy = K[4];
    const float x = (px - cx) / fx, y = (py - cy) / fy;

    float xd, yd;
    if (Dd[6] == 1.0f) {
        float r  = sqrtf(x*x + y*y);
        float th = atanf(r);
        float t2 = th * th;
        float t4 = t2 * t2;
        float rad = th * (1.f + Dd[0]*t2 + Dd[1]*t4 + Dd[2]*t4*t2 + Dd[5]*t4*t4) / r;
        xd = x * rad * fx + cx;
        yd = y * rad * fy + cy;
    } else {
        float r2 = x*x + y*y;
        float r4 = r2 * r2;
        float poly = 1.f + Dd[0]*r2 + Dd[1]*r4 + Dd[2]*r4*r2;
        float p1 = Dd[3], p2 = Dd[4];
        float xdd = x*poly + (2.f*p1*x*y + p2*(r2 + 2.f*x*x));
        float ydd = y*poly + (p1*(r2 + 2.f*y*y) + 2.f*p2*x*y);
        xd = xdd * fx + cx;
        yd = ydd * fy + cy;
    }
    xd *= posf; yd *= posf;

    const float qx = PR[0]*xd + PR[1]*yd + PT[0];
    const float qy = PR[3]*xd + PR[4]*yd + PT[1];

    float2 o;
    o.x = fminf(fmaxf(2.f*qx - 1.f, -1.f), 1.f);
    o.y = fminf(fmaxf(2.f*qy - 1.f, -1.f), 1.f);
    g_nc[id] = o;
}

// ---------------------------------------------------------------------------
// Kernel 3: fused geometry + DEDUPED gather.
// Geometry (48 tasks/block) dedups texel positions per axis (merging signed
// coefficients, dropping zeros), emits compact (offset, coeff) entries to
// smem. Gather: warp-uniform loop, 1 LDS.64 + 1 LDG.64 + 2 FMA per entry.
// Inactive cam == 0 entries -> sum 0 == reference's masked 0.
// ---------------------------------------------------------------------------
__global__ void __launch_bounds__(256) vox_kernel(float* __restrict__ out) {
    const int nhd = blockIdx.x >> 4;
    const int d   = nhd & 127;
    const int nh  = nhd >> 7;
    const int wd0 = (blockIdx.x & 15) << 3;
    const int tid = threadIdx.y * 32 + threadIdx.x;

    __shared__ float2 s_ent[48 * 16];   // .x = offset (int bits), .y = coeff
    __shared__ int    s_cnt[48];
    __shared__ float  res[C * 9];

    // ---- Geometry phase: one task per thread, task = cam*8 + vy ----
    if (tid < 48) {
        const int cam = tid >> 3, vy = tid & 7;
        const int wd = wd0 + vy;
        const float2* ncp = g_nc + cam * (NY * ZD * XD) + ((size_t)nh * ZD + d) * XD + wd;

        float l = 1e30f, r = -1e30f, tp = 1e30f, bt = -1e30f;
        #pragma unroll
        for (int a = 0; a < 2; a++)
            #pragma unroll
            for (int b = 0; b < 2; b++)
                #pragma unroll
                for (int cc2 = 0; cc2 < 2; cc2++) {
                    float2 p = __ldg(ncp + (a * ZD + b) * XD + cc2);
                    l  = fminf(l,  p.x); r  = fmaxf(r,  p.x);
                    tp = fminf(tp, p.y); bt = fmaxf(bt, p.y);
                }

        const float area = (r - l) * (bt - tp) * (HF * WF * 0.25f) + 1e-6f;
        int nt = 0;
        if (area > 1e-6f) {
            float pxl = fminf(fmaxf((l  + 1.f) * 87.5f, 0.f), 175.f);
            float pxr = fminf(fmaxf((r  + 1.f) * 87.5f, 0.f), 175.f);
            float pyt = fminf(fmaxf((tp + 1.f) * 31.5f, 0.f), 63.f);
            float pyb = fminf(fmaxf((bt + 1.f) * 31.5f, 0.f), 63.f);

            float fxl = floorf(pxl), fxr = floorf(pxr);
            float fyt = floorf(pyt), fyb = floorf(pyb);
            float wxl = pxl - fxl, wxr = pxr - fxr;
            float wyt = pyt - fyt, wyb = pyb - fyb;

            const float inv = 1.0f / area;

            int xs[4], ys[4];
            xs[0] = (int)fxl; xs[1] = min(xs[0] + 1, WF - 1);
            xs[2] = (int)fxr; xs[3] = min(xs[2] + 1, WF - 1);
            ys[0] = (int)fyt; ys[1] = min(ys[0] + 1, HF - 1);
            ys[2] = (int)fyb; ys[3] = min(ys[2] + 1, HF - 1);
            float cxv[4] = {1.f - wxl, wxl, -(1.f - wxr), -wxr};
            float cyv[4] = {(1.f - wyt) * inv, wyt * inv,
                            -(1.f - wyb) * inv, -wyb * inv};

            // axis dedup: merge equal coords (sum coeffs), drop zero coeffs
            int   xsd[4], ysd[4];
            float cxd[4], cyd[4];
            int kx = 0, ky = 0;
            #pragma unroll
            for (int i = 0; i < 4; i++) {
                if (cxv[i] != 0.f) {
                    bool hit = false;
                    #pragma unroll
                    for (int j = 0; j < 4; j++)
                        if (j < kx && xsd[j] == xs[i]) { cxd[j] += cxv[i]; hit = true; }
                    if (!hit) { xsd[kx] = xs[i]; cxd[kx] = cxv[i]; kx++; }
                }
                if (cyv[i] != 0.f) {
                    bool hit = false;
                    #pragma unroll
                    for (int j = 0; j < 4; j++)
                        if (j < ky && ysd[j] == ys[i]) { cyd[j] += cyv[i]; hit = true; }
                    if (!hit) { ysd[ky] = ys[i]; cyd[ky] = cyv[i]; ky++; }
                }
            }

            float2* ent = s_ent + tid * 16;
            for (int i = 0; i < ky; i++) {
                const int   yb = ysd[i] * WF;
                const float cy = cyd[i];
                for (int j = 0; j < kx; j++) {
                    const float cc = cy * cxd[j];
                    if (cc != 0.f) {
                        float2 e;
                        e.x = __int_as_float((yb + xsd[j]) * (C / 2));
                        e.y = cc;
                        ent[nt++] = e;
                    }
                }
            }
        }
        s_cnt[tid] = nt;
    }
    __syncthreads();

    // ---- Gather phase ----
    const int t = threadIdx.x;                   // channel pair
    float m0 = -3.402823466e38f, m1 = -3.402823466e38f;

    #pragma unroll 1
    for (int n = 0; n < NCAM; n++) {
        const int task = n * 8 + threadIdx.y;
        const int nt = s_cnt[task];
        const float2* ent = s_ent + task * 16;
        const float2* base = (const float2*)(g_integ + (size_t)n * HF * WF * C) + t;

        float nx = 0.f, nyv = 0.f;
        #pragma unroll 1
        for (int i = 0; i < nt; i++) {
            const float2 e = ent[i];             // broadcast LDS.64
            const float2 v = __ldg(base + __float_as_int(e.x));
            nx  = fmaf(v.x, e.y, nx);
            nyv = fmaf(v.y, e.y, nyv);
        }
        m0 = fmaxf(m0, nx);
        m1 = fmaxf(m1, nyv);
    }

    // ---- Output staging: coalesced 32B segments ----
    res[(2 * t    ) * 9 + threadIdx.y] = m0;
    res[(2 * t + 1) * 9 + threadIdx.y] = m1;
    __syncthreads();

    #pragma unroll
    for (int rep = 0; rep < 2; rep++) {
        int idx = tid + rep * 256;               // 0..511 = c*8 + j
        int ch  = idx >> 3;
        int j   = idx & 7;
        out[((size_t)(ch * NH + nh) * DD + d) * WDIM + wd0 + j] = res[ch * 9 + j];
    }
}

// ---------------------------------------------------------------------------
extern "C" void kernel_launch(void* const* d_in, const int* in_sizes, int n_in,
                              void* d_out, int out_size) {
    (void)in_sizes; (void)n_in; (void)out_size;
    const float* features  = (const float*)d_in[0];
    const float* ks        = (const float*)d_in[1];
    const float* imu2cs    = (const float*)d_in[2];
    const float* post_rots = (const float*)d_in[3];
    const float* post_trans= (const float*)d_in[4];
    const float* undists   = (const float*)d_in[5];
    const float* grid      = (const float*)d_in[6];
    float* out = (float*)d_out;

    integral_kernel<<<NCAM * C, 256>>>(features);

    dim3 tgrid((WF + 31) / 32, HF, NCAM);
    transpose_kernel<<<tgrid, 256>>>();

    const int totalP = NCAM * NY * ZD * XD;
    proj_kernel<<<(totalP + 255) / 256, 256>>>(ks, imu2cs, post_rots, post_trans,
                                               undists, grid);

    dim3 blk(32, 8);
    vox_kernel<<<(NH * DD * WDIM) / 8, blk>>>(out);
}

// round 9
// speedup vs baseline: 1.0361x; 1.0361x over previous
#include <cuda_runtime.h>

#define NCAM 6
#define C    64
#define HF   64
#define WF   176
#define NY   4
#define ZD   129
#define XD   129
#define NH   3
#define DD   128
#define WDIM 128
#define NVOX (NH * DD * WDIM)   // 49152

// Scratch (static device globals: allocation-free per harness rules)
__device__ float  g_tmpi[NCAM * C * HF * WF];    // [n][c][h][w]
__device__ float  g_integ[NCAM * HF * WF * C];   // [n][h][w][c]
__device__ float2 g_nc[NCAM * NY * ZD * XD];     // projected corners

// ---------------------------------------------------------------------------
// Kernel 1: integral image per (n,c), coalesced channel-major write
// ---------------------------------------------------------------------------
__global__ void __launch_bounds__(256) integral_kernel(const float* __restrict__ feat) {
    __shared__ float tile[HF * WF];
    const int ncid = blockIdx.x;
    const int tid = threadIdx.x;

    const float* src = feat + (size_t)ncid * HF * WF;
    for (int i = tid; i < HF * WF; i += 256) tile[i] = src[i];
    __syncthreads();

    const int lane = tid & 31, wp = tid >> 5;
    for (int row = wp; row < HF; row += 8) {
        float carry = 0.f;
        #pragma unroll
        for (int seg = 0; seg < 6; seg++) {
            int w = seg * 32 + lane;
            float v = (w < WF) ? tile[row * WF + w] : 0.f;
            #pragma unroll
            for (int off = 1; off < 32; off <<= 1) {
                float u = __shfl_up_sync(0xffffffffu, v, off);
                if (lane >= off) v += u;
            }
            v += carry;
            if (w < WF) tile[row * WF + w] = v;
            carry = __shfl_sync(0xffffffffu, v, 31);
        }
    }
    __syncthreads();

    if (tid < WF) {
        float acc = 0.f;
        #pragma unroll 4
        for (int h = 0; h < HF; h++) {
            acc += tile[h * WF + tid];
            tile[h * WF + tid] = acc;
        }
    }
    __syncthreads();

    float* dst = g_tmpi + (size_t)ncid * HF * WF;
    for (int i = tid; i < HF * WF; i += 256) dst[i] = tile[i];
}

// ---------------------------------------------------------------------------
// Kernel 1b: transpose [n][c][h][w] -> [n][h][w][c]
// ---------------------------------------------------------------------------
__global__ void __launch_bounds__(256) transpose_kernel() {
    __shared__ float tile[C * 33];
    const int n  = blockIdx.z;
    const int h  = blockIdx.y;
    const int w0 = blockIdx.x * 32;

    const float* src = g_tmpi + ((size_t)n * C * HF + h) * WF;
    for (int idx = threadIdx.x; idx < C * 32; idx += 256) {
        int c = idx >> 5, w = idx & 31;
        int gw = w0 + w;
        tile[c * 33 + w] = (gw < WF) ? src[(size_t)c * HF * WF + gw] : 0.f;
    }
    __syncthreads();

    float* dst = g_integ + (((size_t)n * HF + h) * WF) * C;
    for (int idx = threadIdx.x; idx < C * 32; idx += 256) {
        int w = idx >> 6, c = idx & 63;
        int gw = w0 + w;
        if (gw < WF) dst[(size_t)gw * C + c] = tile[c * 33 + w];
    }
}

// ---------------------------------------------------------------------------
// Kernel 2: project grid corners
// ---------------------------------------------------------------------------
__global__ void proj_kernel(const float* __restrict__ ks,
                            const float* __restrict__ m2c,
                            const float* __restrict__ prot,
                            const float* __restrict__ ptran,
                            const float* __restrict__ und,
                            const float* __restrict__ grid) {
    const int id = blockIdx.x * blockDim.x + threadIdx.x;
    const int total = NCAM * NY * ZD * XD;
    if (id >= total) return;
    const int xi = id % XD;
    const int zi = (id / XD) % ZD;
    const int ny = (id / (XD * ZD)) % NY;
    const int n  = id / (XD * ZD * NY);

    const float* K  = ks    + n * 9;
    const float* M  = m2c   + n * 12;
    const float* PR = prot  + n * 9;
    const float* PT = ptran + n * 3;
    const float* Dd = und   + n * 7;

    float cal[3][4];
    #pragma unroll
    for (int i = 0; i < 3; i++)
        #pragma unroll
        for (int j = 0; j < 4; j++)
            cal[i][j] = K[i*3+0]*M[0*4+j] + K[i*3+1]*M[1*4+j] + K[i*3+2]*M[2*4+j];

    const float* g = grid + ((size_t)zi * XD + xi) * 3;
    const float vx = g[0];
    const float vy = g[1] + (2.0f - (float)ny);
    const float vz = g[2];

    float hx = cal[0][0]*vx + cal[0][1]*vy + cal[0][2]*vz + cal[0][3];
    float hy = cal[1][0]*vx + cal[1][1]*vy + cal[1][2]*vz + cal[1][3];
    float hz = cal[2][0]*vx + cal[2][1]*vy + cal[2][2]*vz + cal[2][3];

    const float posf = (hz > 0.f) ? 1.f : 0.f;
    hx *= posf; hy *= posf;
    const float px = hx / hz, py = hy / hz;

    const float cx = K[2], cy = K[5], fx = K[0], fy = K[4];
    const float x = (px - cx) / fx, y = (py - cy) / fy;

    float xd, yd;
    if (Dd[6] == 1.0f) {
        float r  = sqrtf(x*x + y*y);
        float th = atanf(r);
        float t2 = th * th;
        float t4 = t2 * t2;
        float rad = th * (1.f + Dd[0]*t2 + Dd[1]*t4 + Dd[2]*t4*t2 + Dd[5]*t4*t4) / r;
        xd = x * rad * fx + cx;
        yd = y * rad * fy + cy;
    } else {
        float r2 = x*x + y*y;
        float r4 = r2 * r2;
        float poly = 1.f + Dd[0]*r2 + Dd[1]*r4 + Dd[2]*r4*r2;
        float p1 = Dd[3], p2 = Dd[4];
        float xdd = x*poly + (2.f*p1*x*y + p2*(r2 + 2.f*x*x));
        float ydd = y*poly + (p1*(r2 + 2.f*y*y) + 2.f*p2*x*y);
        xd = xdd * fx + cx;
        yd = ydd * fy + cy;
    }
    xd *= posf; yd *= posf;

    const float qx = PR[0]*xd + PR[1]*yd + PT[0];
    const float qy = PR[3]*xd + PR[4]*yd + PT[1];

    float2 o;
    o.x = fminf(fmaxf(2.f*qx - 1.f, -1.f), 1.f);
    o.y = fminf(fmaxf(2.f*qy - 1.f, -1.f), 1.f);
    g_nc[id] = o;
}

// ---------------------------------------------------------------------------
// Kernel 3: fused geometry + deduped FIXED-SHAPE gather.
// Geometry dedups per axis into <=4 x-cols and <=4 y-rows (signed coeffs
// merged, 1/area folded). Gather is a fully unrolled 4x4 nest with
// warp-uniform count guards: skipped loads cost nothing, taken loads are
// independent (high MLP).
// ---------------------------------------------------------------------------
__global__ void __launch_bounds__(256) vox_kernel(float* __restrict__ out) {
    const int nhd = blockIdx.x >> 4;
    const int d   = nhd & 127;
    const int nh  = nhd >> 7;
    const int wd0 = (blockIdx.x & 15) << 3;
    const int tid = threadIdx.y * 32 + threadIdx.x;

    __shared__ int4   s_x[48];     // x offsets (float2 units), padded w/ dup
    __shared__ int4   s_y[48];     // y row offsets (float2 units)
    __shared__ float4 s_cx[48];    // merged x coeffs (pad 0)
    __shared__ float4 s_cy[48];    // merged y coeffs * inv_area (pad 0)
    __shared__ int    s_k[48];     // kx | (ky<<4); 0 = inactive
    __shared__ float  res[C * 9];

    // ---- Geometry phase: one task per thread, task = cam*8 + vy ----
    if (tid < 48) {
        const int cam = tid >> 3, vy = tid & 7;
        const int wd = wd0 + vy;
        const float2* ncp = g_nc + cam * (NY * ZD * XD) + ((size_t)nh * ZD + d) * XD + wd;

        float l = 1e30f, r = -1e30f, tp = 1e30f, bt = -1e30f;
        #pragma unroll
        for (int a = 0; a < 2; a++)
            #pragma unroll
            for (int b = 0; b < 2; b++)
                #pragma unroll
                for (int cc2 = 0; cc2 < 2; cc2++) {
                    float2 p = __ldg(ncp + (a * ZD + b) * XD + cc2);
                    l  = fminf(l,  p.x); r  = fmaxf(r,  p.x);
                    tp = fminf(tp, p.y); bt = fmaxf(bt, p.y);
                }

        const float area = (r - l) * (bt - tp) * (HF * WF * 0.25f) + 1e-6f;
        int kpack = 0;
        if (area > 1e-6f) {
            float pxl = fminf(fmaxf((l  + 1.f) * 87.5f, 0.f), 175.f);
            float pxr = fminf(fmaxf((r  + 1.f) * 87.5f, 0.f), 175.f);
            float pyt = fminf(fmaxf((tp + 1.f) * 31.5f, 0.f), 63.f);
            float pyb = fminf(fmaxf((bt + 1.f) * 31.5f, 0.f), 63.f);

            float fxl = floorf(pxl), fxr = floorf(pxr);
            float fyt = floorf(pyt), fyb = floorf(pyb);
            float wxl = pxl - fxl, wxr = pxr - fxr;
            float wyt = pyt - fyt, wyb = pyb - fyb;

            const float inv = 1.0f / area;

            int xs[4], ys[4];
            xs[0] = (int)fxl; xs[1] = min(xs[0] + 1, WF - 1);
            xs[2] = (int)fxr; xs[3] = min(xs[2] + 1, WF - 1);
            ys[0] = (int)fyt; ys[1] = min(ys[0] + 1, HF - 1);
            ys[2] = (int)fyb; ys[3] = min(ys[2] + 1, HF - 1);
            float cxv[4] = {1.f - wxl, wxl, -(1.f - wxr), -wxr};
            float cyv[4] = {(1.f - wyt) * inv, wyt * inv,
                            -(1.f - wyb) * inv, -wyb * inv};

            // axis dedup: merge equal coords (sum coeffs), drop zero coeffs
            int   xsd[4] = {0,0,0,0}, ysd[4] = {0,0,0,0};
            float cxd[4] = {0,0,0,0}, cyd[4] = {0,0,0,0};
            int kx = 0, ky = 0;
            #pragma unroll
            for (int i = 0; i < 4; i++) {
                if (cxv[i] != 0.f) {
                    bool hit = false;
                    #pragma unroll
                    for (int j = 0; j < 4; j++)
                        if (j < kx && xsd[j] == xs[i]) { cxd[j] += cxv[i]; hit = true; }
                    if (!hit) { xsd[kx] = xs[i]; cxd[kx] = cxv[i]; kx++; }
                }
                if (cyv[i] != 0.f) {
                    bool hit = false;
                    #pragma unroll
                    for (int j = 0; j < 4; j++)
                        if (j < ky && ysd[j] == ys[i]) { cyd[j] += cyv[i]; hit = true; }
                    if (!hit) { ysd[ky] = ys[i]; cyd[ky] = cyv[i]; ky++; }
                }
            }
            // pad coords with entry 0 (coeff already 0)
            #pragma unroll
            for (int i = 0; i < 4; i++) {
                if (i >= kx) xsd[i] = xsd[0];
                if (i >= ky) ysd[i] = ysd[0];
            }
            s_x[tid]  = make_int4(xsd[0] * (C/2), xsd[1] * (C/2),
                                  xsd[2] * (C/2), xsd[3] * (C/2));
            s_y[tid]  = make_int4(ysd[0] * WF * (C/2), ysd[1] * WF * (C/2),
                                  ysd[2] * WF * (C/2), ysd[3] * WF * (C/2));
            s_cx[tid] = make_float4(cxd[0], cxd[1], cxd[2], cxd[3]);
            s_cy[tid] = make_float4(cyd[0], cyd[1], cyd[2], cyd[3]);
            kpack = kx | (ky << 4);
        }
        s_k[tid] = kpack;
    }
    __syncthreads();

    // ---- Gather phase ----
    const int t = threadIdx.x;                   // channel pair
    float m0 = -3.402823466e38f, m1 = -3.402823466e38f;

    #pragma unroll 1
    for (int n = 0; n < NCAM; n++) {
        const int task = n * 8 + threadIdx.y;
        const int kp = s_k[task];
        if (kp == 0) {
            m0 = fmaxf(m0, 0.f);
            m1 = fmaxf(m1, 0.f);
            continue;
        }
        const int kx = kp & 15, ky = kp >> 4;
        const int4   xo = s_x[task];
        const int4   yo = s_y[task];
        const float4 cx = s_cx[task];
        const float4 cy = s_cy[task];
        const int xoa[4] = {xo.x, xo.y, xo.z, xo.w};
        const int yoa[4] = {yo.x, yo.y, yo.z, yo.w};
        const float cxa[4] = {cx.x, cx.y, cx.z, cx.w};
        const float cya[4] = {cy.x, cy.y, cy.z, cy.w};

        const float2* base = (const float2*)(g_integ + (size_t)n * HF * WF * C) + t;

        float nx = 0.f, nyv = 0.f;
        #pragma unroll
        for (int i = 0; i < 4; i++) {
            if (i < ky) {                        // warp-uniform guard
                const float2* rb = base + yoa[i];
                float2 v0 = __ldg(rb + xoa[0]);
                float rx = v0.x * cxa[0];
                float ry = v0.y * cxa[0];
                if (kx > 1) {
                    float2 v1 = __ldg(rb + xoa[1]);
                    rx = fmaf(v1.x, cxa[1], rx);
                    ry = fmaf(v1.y, cxa[1], ry);
                }
                if (kx > 2) {
                    float2 v2 = __ldg(rb + xoa[2]);
                    rx = fmaf(v2.x, cxa[2], rx);
                    ry = fmaf(v2.y, cxa[2], ry);
                }
                if (kx > 3) {
                    float2 v3 = __ldg(rb + xoa[3]);
                    rx = fmaf(v3.x, cxa[3], rx);
                    ry = fmaf(v3.y, cxa[3], ry);
                }
                nx  = fmaf(rx, cya[i], nx);
                nyv = fmaf(ry, cya[i], nyv);
            }
        }
        m0 = fmaxf(m0, nx);
        m1 = fmaxf(m1, nyv);
    }

    // ---- Output staging: coalesced 32B segments ----
    res[(2 * t    ) * 9 + threadIdx.y] = m0;
    res[(2 * t + 1) * 9 + threadIdx.y] = m1;
    __syncthreads();

    #pragma unroll
    for (int rep = 0; rep < 2; rep++) {
        int idx = tid + rep * 256;               // 0..511 = c*8 + j
        int ch  = idx >> 3;
        int j   = idx & 7;
        out[((size_t)(ch * NH + nh) * DD + d) * WDIM + wd0 + j] = res[ch * 9 + j];
    }
}

// ---------------------------------------------------------------------------
extern "C" void kernel_launch(void* const* d_in, const int* in_sizes, int n_in,
                              void* d_out, int out_size) {
    (void)in_sizes; (void)n_in; (void)out_size;
    const float* features  = (const float*)d_in[0];
    const float* ks        = (const float*)d_in[1];
    const float* imu2cs    = (const float*)d_in[2];
    const float* post_rots = (const float*)d_in[3];
    const float* post_trans= (const float*)d_in[4];
    const float* undists   = (const float*)d_in[5];
    const float* grid      = (const float*)d_in[6];
    float* out = (float*)d_out;

    integral_kernel<<<NCAM * C, 256>>>(features);

    dim3 tgrid((WF + 31) / 32, HF, NCAM);
    transpose_kernel<<<tgrid, 256>>>();

    const int totalP = NCAM * NY * ZD * XD;
    proj_kernel<<<(totalP + 255) / 256, 256>>>(ks, imu2cs, post_rots, post_trans,
                                               undists, grid);

    dim3 blk(32, 8);
    vox_kernel<<<(NH * DD * WDIM) / 8, blk>>>(out);
}

// round 11
// speedup vs baseline: 1.1702x; 1.1294x over previous
#include <cuda_runtime.h>

#define NCAM 6
#define C    64
#define HF   64
#define WF   176
#define NY   4
#define ZD   129
#define XD   129
#define NH   3
#define DD   128
#define WDIM 128
#define NVOX (NH * DD * WDIM)   // 49152
#define TPITCH 177              // padded smem row stride (odd mod 32)

// Scratch (static device globals: allocation-free per harness rules)
__device__ float  g_tmpi[NCAM * C * HF * WF];    // [n][c][h][w]
__device__ float  g_integ[NCAM * HF * WF * C];   // [n][h][w][c]
__device__ float2 g_nc[NCAM * NY * ZD * XD];     // projected corners

// ---------------------------------------------------------------------------
// Kernel 1: integral image per (n,c). Row scan AND column scan both via
// warp shuffles on a stride-177 padded tile (conflict-free both ways).
// ---------------------------------------------------------------------------
__global__ void __launch_bounds__(256) integral_kernel(const float* __restrict__ feat) {
    __shared__ float tile[HF * TPITCH];          // 45312 B
    const int ncid = blockIdx.x;
    const int tid = threadIdx.x;
    const int lane = tid & 31, wp = tid >> 5;

    const float* src = feat + (size_t)ncid * HF * WF;
    for (int i = tid; i < HF * WF; i += 256) {
        int h = i / WF, w = i - h * WF;
        tile[h * TPITCH + w] = src[i];
    }
    __syncthreads();

    // Row-wise inclusive scan: warp wp handles rows wp, wp+8, ...
    for (int row = wp; row < HF; row += 8) {
        float carry = 0.f;
        #pragma unroll
        for (int seg = 0; seg < 6; seg++) {
            int w = seg * 32 + lane;
            float v = (w < WF) ? tile[row * TPITCH + w] : 0.f;
            #pragma unroll
            for (int off = 1; off < 32; off <<= 1) {
                float u = __shfl_up_sync(0xffffffffu, v, off);
                if (lane >= off) v += u;
            }
            v += carry;
            if (w < WF) tile[row * TPITCH + w] = v;
            carry = __shfl_sync(0xffffffffu, v, 31);
        }
    }
    __syncthreads();

    // Column-wise inclusive scan: warp wp handles columns wp, wp+8, ...
    // lanes = h; stride TPITCH (odd) -> bank-conflict-free.
    for (int w = wp; w < WF; w += 8) {
        float carry = 0.f;
        #pragma unroll
        for (int seg = 0; seg < 2; seg++) {
            int h = seg * 32 + lane;
            float v = tile[h * TPITCH + w];
            #pragma unroll
            for (int off = 1; off < 32; off <<= 1) {
                float u = __shfl_up_sync(0xffffffffu, v, off);
                if (lane >= off) v += u;
            }
            v += carry;
            tile[h * TPITCH + w] = v;
            carry = __shfl_sync(0xffffffffu, v, 31);
        }
    }
    __syncthreads();

    float* dst = g_tmpi + (size_t)ncid * HF * WF;
    for (int i = tid; i < HF * WF; i += 256) {
        int h = i / WF, w = i - h * WF;
        dst[i] = tile[h * TPITCH + w];
    }
}

// ---------------------------------------------------------------------------
// Kernel 2 (fused): blocks [0, 2304) transpose [n][c][h][w] -> [n][h][w][c];
// blocks [2304, ...) project grid corners. Independent work, one launch.
// ---------------------------------------------------------------------------
#define NTRANS (6 * HF * NCAM)   // 2304 transpose blocks
__global__ void __launch_bounds__(256) transproj_kernel(
        const float* __restrict__ ks,
        const float* __restrict__ m2c,
        const float* __restrict__ prot,
        const float* __restrict__ ptran,
        const float* __restrict__ und,
        const float* __restrict__ grid) {
    __shared__ float tile[C * 33];
    const int bid = blockIdx.x;

    if (bid < NTRANS) {
        // ---- transpose ----
        const int wt = bid % 6;
        const int h  = (bid / 6) % HF;
        const int n  = bid / (6 * HF);
        const int w0 = wt * 32;

        const float* src = g_tmpi + ((size_t)n * C * HF + h) * WF;
        for (int idx = threadIdx.x; idx < C * 32; idx += 256) {
            int c = idx >> 5, w = idx & 31;
            int gw = w0 + w;
            tile[c * 33 + w] = (gw < WF) ? src[(size_t)c * HF * WF + gw] : 0.f;
        }
        __syncthreads();

        float* dst = g_integ + (((size_t)n * HF + h) * WF) * C;
        for (int idx = threadIdx.x; idx < C * 32; idx += 256) {
            int w = idx >> 6, c = idx & 63;
            int gw = w0 + w;
            if (gw < WF) dst[(size_t)gw * C + c] = tile[c * 33 + w];
        }
        return;
    }

    // ---- projection ----
    const int id = (bid - NTRANS) * 256 + threadIdx.x;
    const int total = NCAM * NY * ZD * XD;
    if (id >= total) return;
    const int xi = id % XD;
    const int zi = (id / XD) % ZD;
    const int ny = (id / (XD * ZD)) % NY;
    const int n  = id / (XD * ZD * NY);

    const float* K  = ks    + n * 9;
    const float* M  = m2c   + n * 12;
    const float* PR = prot  + n * 9;
    const float* PT = ptran + n * 3;
    const float* Dd = und   + n * 7;

    float cal[3][4];
    #pragma unroll
    for (int i = 0; i < 3; i++)
        #pragma unroll
        for (int j = 0; j < 4; j++)
            cal[i][j] = K[i*3+0]*M[0*4+j] + K[i*3+1]*M[1*4+j] + K[i*3+2]*M[2*4+j];

    const float* g = grid + ((size_t)zi * XD + xi) * 3;
    const float vx = g[0];
    const float vy = g[1] + (2.0f - (float)ny);
    const float vz = g[2];

    float hx = cal[0][0]*vx + cal[0][1]*vy + cal[0][2]*vz + cal[0][3];
    float hy = cal[1][0]*vx + cal[1][1]*vy + cal[1][2]*vz + cal[1][3];
    float hz = cal[2][0]*vx + cal[2][1]*vy + cal[2][2]*vz + cal[2][3];

    const float posf = (hz > 0.f) ? 1.f : 0.f;
    hx *= posf; hy *= posf;
    const float px = hx / hz, py = hy / hz;

    const float cx = K[2], cy = K[5], fx = K[0], fy = K[4];
    const float x = (px - cx) / fx, y = (py - cy) / fy;

    float xd, yd;
    if (Dd[6] == 1.0f) {
        float r  = sqrtf(x*x + y*y);
        float th = atanf(r);
        float t2 = th * th;
        float t4 = t2 * t2;
        float rad = th * (1.f + Dd[0]*t2 + Dd[1]*t4 + Dd[2]*t4*t2 + Dd[5]*t4*t4) / r;
        xd = x * rad * fx + cx;
        yd = y * rad * fy + cy;
    } else {
        float r2 = x*x + y*y;
        float r4 = r2 * r2;
        float poly = 1.f + Dd[0]*r2 + Dd[1]*r4 + Dd[2]*r4*r2;
        float p1 = Dd[3], p2 = Dd[4];
        float xdd = x*poly + (2.f*p1*x*y + p2*(r2 + 2.f*x*x));
        float ydd = y*poly + (p1*(r2 + 2.f*y*y) + 2.f*p2*x*y);
        xd = xdd * fx + cx;
        yd = ydd * fy + cy;
    }
    xd *= posf; yd *= posf;

    const float qx = PR[0]*xd + PR[1]*yd + PT[0];
    const float qy = PR[3]*xd + PR[4]*yd + PT[1];

    float2 o;
    o.x = fminf(fmaxf(2.f*qx - 1.f, -1.f), 1.f);
    o.y = fminf(fmaxf(2.f*qy - 1.f, -1.f), 1.f);
    g_nc[id] = o;
}

// ---------------------------------------------------------------------------
// Kernel 3 (R6 proven form): fused geometry (smem descriptors, 48 tasks per
// block) + gather. 16 independent unrolled loads per cam, coefficients
// pre-combined with 1/area; max over cameras.
// ---------------------------------------------------------------------------
__global__ void __launch_bounds__(256) vox_kernel(float* __restrict__ out) {
    const int nhd = blockIdx.x >> 4;
    const int d   = nhd & 127;
    const int nh  = nhd >> 7;
    const int wd0 = (blockIdx.x & 15) << 3;
    const int tid = threadIdx.y * 32 + threadIdx.x;

    __shared__ int   s_off[48 * 16];    // texel offsets (float2 units)
    __shared__ float s_c[48 * 16];      // combined coefficients
    __shared__ int   s_act[48];         // active flag per (cam,voxel)
    __shared__ float res[C * 9];        // output staging

    // ---- Geometry phase: one task per thread, task = cam*8 + vy ----
    if (tid < 48) {
        const int cam = tid >> 3, vy = tid & 7;
        const int wd = wd0 + vy;
        const float2* ncp = g_nc + cam * (NY * ZD * XD) + ((size_t)nh * ZD + d) * XD + wd;

        float l = 1e30f, r = -1e30f, tp = 1e30f, bt = -1e30f;
        #pragma unroll
        for (int a = 0; a < 2; a++)
            #pragma unroll
            for (int b = 0; b < 2; b++)
                #pragma unroll
                for (int cc2 = 0; cc2 < 2; cc2++) {
                    float2 p = __ldg(ncp + (a * ZD + b) * XD + cc2);
                    l  = fminf(l,  p.x); r  = fmaxf(r,  p.x);
                    tp = fminf(tp, p.y); bt = fmaxf(bt, p.y);
                }

        const float area = (r - l) * (bt - tp) * (HF * WF * 0.25f) + 1e-6f;
        const int ok = (area > 1e-6f) ? 1 : 0;
        s_act[tid] = ok;
        if (ok) {
            float pxl = fminf(fmaxf((l  + 1.f) * 87.5f, 0.f), 175.f);
            float pxr = fminf(fmaxf((r  + 1.f) * 87.5f, 0.f), 175.f);
            float pyt = fminf(fmaxf((tp + 1.f) * 31.5f, 0.f), 63.f);
            float pyb = fminf(fmaxf((bt + 1.f) * 31.5f, 0.f), 63.f);

            float fxl = floorf(pxl), fxr = floorf(pxr);
            float fyt = floorf(pyt), fyb = floorf(pyb);
            float wxl = pxl - fxl, wxr = pxr - fxr;
            float wyt = pyt - fyt, wyb = pyb - fyb;

            int xs[4], ys[4];
            xs[0] = (int)fxl; xs[1] = min(xs[0] + 1, WF - 1);
            xs[2] = (int)fxr; xs[3] = min(xs[2] + 1, WF - 1);
            ys[0] = (int)fyt; ys[1] = min(ys[0] + 1, HF - 1);
            ys[2] = (int)fyb; ys[3] = min(ys[2] + 1, HF - 1);

            const float inv = 1.0f / area;
            float cxv[4] = {1.f - wxl, wxl, -(1.f - wxr), -wxr};
            float cyv[4] = {(1.f - wyt) * inv, wyt * inv,
                            -(1.f - wyb) * inv, -wyb * inv};

            #pragma unroll
            for (int i = 0; i < 4; i++) {
                const int yb = ys[i] * WF;
                #pragma unroll
                for (int j = 0; j < 4; j++) {
                    s_off[tid * 16 + i * 4 + j] = (yb + xs[j]) * (C / 2);
                    s_c[tid * 16 + i * 4 + j]   = cyv[i] * cxv[j];
                }
            }
        }
    }
    __syncthreads();

    // ---- Gather phase ----
    const int t = threadIdx.x;                   // channel pair
    float m0 = -3.402823466e38f, m1 = -3.402823466e38f;

    #pragma unroll 1
    for (int n = 0; n < NCAM; n++) {
        const int task = n * 8 + threadIdx.y;
        if (!s_act[task]) {
            m0 = fmaxf(m0, 0.f);
            m1 = fmaxf(m1, 0.f);
            continue;
        }
        const int4*   so = (const int4*)  (s_off + task * 16);
        const float4* sc = (const float4*)(s_c   + task * 16);
        const float2* base = (const float2*)(g_integ + (size_t)n * HF * WF * C) + t;

        float nx = 0.f, nyv = 0.f;
        #pragma unroll
        for (int g = 0; g < 4; g++) {
            const int4   o  = so[g];
            const float4 cc = sc[g];
            float2 a = __ldg(base + o.x), b = __ldg(base + o.y);
            float2 c = __ldg(base + o.z), e = __ldg(base + o.w);
            nx  = fmaf(a.x, cc.x, fmaf(b.x, cc.y, fmaf(c.x, cc.z, fmaf(e.x, cc.w, nx))));
            nyv = fmaf(a.y, cc.x, fmaf(b.y, cc.y, fmaf(c.y, cc.z, fmaf(e.y, cc.w, nyv))));
        }
        m0 = fmaxf(m0, nx);
        m1 = fmaxf(m1, nyv);
    }

    // ---- Output staging: coalesced 32B segments ----
    res[(2 * t    ) * 9 + threadIdx.y] = m0;
    res[(2 * t + 1) * 9 + threadIdx.y] = m1;
    __syncthreads();

    #pragma unroll
    for (int rep = 0; rep < 2; rep++) {
        int idx = tid + rep * 256;               // 0..511 = c*8 + j
        int ch  = idx >> 3;
        int j   = idx & 7;
        out[((size_t)(ch * NH + nh) * DD + d) * WDIM + wd0 + j] = res[ch * 9 + j];
    }
}

// ---------------------------------------------------------------------------
extern "C" void kernel_launch(void* const* d_in, const int* in_sizes, int n_in,
                              void* d_out, int out_size) {
    (void)in_sizes; (void)n_in; (void)out_size;
    const float* features  = (const float*)d_in[0];
    const float* ks        = (const float*)d_in[1];
    const float* imu2cs    = (const float*)d_in[2];
    const float* post_rots = (const float*)d_in[3];
    const float* post_trans= (const float*)d_in[4];
    const float* undists   = (const float*)d_in[5];
    const float* grid      = (const float*)d_in[6];
    float* out = (float*)d_out;

    integral_kernel<<<NCAM * C, 256>>>(features);

    const int totalP = NCAM * NY * ZD * XD;
    const int projBlocks = (totalP + 255) / 256;     // 1561
    transproj_kernel<<<NTRANS + projBlocks, 256>>>(ks, imu2cs, post_rots,
                                                   post_trans, undists, grid);

    dim3 blk(32, 8);
    vox_kernel<<<(NH * DD * WDIM) / 8, blk>>>(out);
}